// round 1
// baseline (speedup 1.0000x reference)
#include <cuda_runtime.h>
#include <cuda_bf16.h>
#include <math.h>

// ---------------- problem constants ----------------
#define BB    8
#define LL    2048
#define VOCABN 1969
#define DM    768
#define NL    4
#define DI    1536
#define DS    16
#define DCONV 4
#define DTR   48
#define MTOT  (BB*LL)          // 16384
#define XD    80               // DT_RANK + 2*D_STATE
#define EPSV  1e-5f

// ---------------- scratch (device globals; no allocs allowed) ----------------
__device__ float g_h    [MTOT*DM];       // residual stream
__device__ float g_xn   [MTOT*DM];       // rmsnorm output
__device__ float g_xz   [MTOT*2*DI];     // in_proj output
__device__ float g_x    [MTOT*DI];       // conv+silu output (u)
__device__ float g_xdbl [MTOT*XD];       // x_proj output (dt | B | C)
__device__ float g_delta[MTOT*DI];       // softplus(dt_proj)
__device__ float g_y    [MTOT*DI];       // scan output (gated)

// ---------------- helpers ----------------
__device__ __forceinline__ float silu_f(float v) {
    return v / (1.0f + __expf(-v));
}
__device__ __forceinline__ float softplus_f(float v) {
    return fmaxf(v, 0.0f) + log1pf(__expf(-fabsf(v)));
}

// ---------------- embedding + time embedding ----------------
__global__ void embed_kernel(const int* __restrict__ ids,
                             const float* __restrict__ times,
                             const float* __restrict__ embed,
                             const float* __restrict__ time_w,
                             const float* __restrict__ time_b,
                             float* __restrict__ h)
{
    int idx = blockIdx.x * blockDim.x + threadIdx.x;
    if (idx >= MTOT * DM) return;
    int t = idx / DM;
    int d = idx - t * DM;
    int tok = ids[t];
    h[idx] = embed[(size_t)tok * DM + d] + times[t] * time_w[d] + time_b[d];
}

// ---------------- rmsnorm (one block per row of 768) ----------------
__global__ void __launch_bounds__(256) rmsnorm_kernel(const float* __restrict__ in,
                                                      const float* __restrict__ w,
                                                      float* __restrict__ out)
{
    __shared__ float red[256];
    int r = blockIdx.x;
    int tid = threadIdx.x;
    const float* row = in + (size_t)r * DM;
    float v0 = row[tid];
    float v1 = row[tid + 256];
    float v2 = row[tid + 512];
    float ss = v0*v0 + v1*v1 + v2*v2;
    red[tid] = ss;
    __syncthreads();
    for (int s = 128; s > 0; s >>= 1) {
        if (tid < s) red[tid] += red[tid + s];
        __syncthreads();
    }
    float scale = rsqrtf(red[0] * (1.0f / DM) + EPSV);
    float* orow = out + (size_t)r * DM;
    orow[tid]       = v0 * scale * w[tid];
    orow[tid + 256] = v1 * scale * w[tid + 256];
    orow[tid + 512] = v2 * scale * w[tid + 512];
}

// ---------------- generic NT SGEMM: C[M,N] = A[M,K] @ W[N,K]^T ----------------
// 128x128 tile, BK=8, 256 threads, 8x8 microtile.
// Requirements satisfied by all call sites: M % 128 == 0, K % 8 == 0,
// lda % 4 == 0, K % 4 == 0 (float4 loads). N guarded.
template<bool BIAS, bool SOFTPLUS, bool RESID>
__global__ void __launch_bounds__(256) gemm_nt(const float* __restrict__ A,
                                               const float* __restrict__ W,
                                               float* __restrict__ C,
                                               int M, int N, int K,
                                               int lda, int ldc,
                                               const float* __restrict__ bias)
{
    __shared__ float As[8][128];
    __shared__ float Bs[8][128];

    int tid  = threadIdx.x;
    int bm   = blockIdx.y * 128;
    int bn   = blockIdx.x * 128;
    int lrow = tid >> 1;              // 0..127
    int lcol = (tid & 1) * 4;         // 0 or 4
    int tx   = tid & 15;              // col group
    int ty   = tid >> 4;              // row group

    const float* Aptr  = A + (size_t)(bm + lrow) * lda + lcol;
    const float* Bptr  = W + (size_t)(bn + lrow) * K   + lcol;
    bool bvalid = (bn + lrow) < N;

    float acc[8][8];
    #pragma unroll
    for (int i = 0; i < 8; i++)
        #pragma unroll
        for (int j = 0; j < 8; j++)
            acc[i][j] = 0.0f;

    for (int k0 = 0; k0 < K; k0 += 8) {
        float4 av = *(const float4*)(Aptr + k0);
        float4 bv = bvalid ? *(const float4*)(Bptr + k0)
                           : make_float4(0.f, 0.f, 0.f, 0.f);
        __syncthreads();
        As[lcol + 0][lrow] = av.x;
        As[lcol + 1][lrow] = av.y;
        As[lcol + 2][lrow] = av.z;
        As[lcol + 3][lrow] = av.w;
        Bs[lcol + 0][lrow] = bv.x;
        Bs[lcol + 1][lrow] = bv.y;
        Bs[lcol + 2][lrow] = bv.z;
        Bs[lcol + 3][lrow] = bv.w;
        __syncthreads();
        #pragma unroll
        for (int k = 0; k < 8; k++) {
            float a[8], b[8];
            *(float4*)(a)     = *(const float4*)&As[k][ty * 8];
            *(float4*)(a + 4) = *(const float4*)&As[k][ty * 8 + 4];
            *(float4*)(b)     = *(const float4*)&Bs[k][tx * 8];
            *(float4*)(b + 4) = *(const float4*)&Bs[k][tx * 8 + 4];
            #pragma unroll
            for (int i = 0; i < 8; i++)
                #pragma unroll
                for (int j = 0; j < 8; j++)
                    acc[i][j] = fmaf(a[i], b[j], acc[i][j]);
        }
    }

    #pragma unroll
    for (int i = 0; i < 8; i++) {
        int m = bm + ty * 8 + i;
        #pragma unroll
        for (int j = 0; j < 8; j++) {
            int n = bn + tx * 8 + j;
            if (n < N) {
                float v = acc[i][j];
                if (BIAS)     v += bias[n];
                if (SOFTPLUS) v = softplus_f(v);
                size_t idx = (size_t)m * ldc + n;
                if (RESID)    v += C[idx];
                C[idx] = v;
            }
        }
    }
}

// ---------------- causal depthwise conv (width 4) + silu ----------------
__global__ void conv_silu_kernel(const float* __restrict__ xz,
                                 const float* __restrict__ cw,
                                 const float* __restrict__ cb,
                                 float* __restrict__ x)
{
    int idx = blockIdx.x * blockDim.x + threadIdx.x;
    if (idx >= MTOT * DI) return;
    int t = idx / DI;
    int d = idx - t * DI;
    int l = t & (LL - 1);          // L = 2048 power of two
    float w0 = cw[d * DCONV + 0];
    float w1 = cw[d * DCONV + 1];
    float w2 = cw[d * DCONV + 2];
    float w3 = cw[d * DCONV + 3];
    float acc = cb[d];
    const float* base = xz + (size_t)t * (2 * DI) + d;
    if (l >= 3) acc += base[-3 * 2 * DI] * w0;
    if (l >= 2) acc += base[-2 * 2 * DI] * w1;
    if (l >= 1) acc += base[-1 * 2 * DI] * w2;
    acc += base[0] * w3;
    x[idx] = silu_f(acc);
}

// ---------------- selective scan (fused D-skip + z gate) ----------------
// grid: (DI/128, B), block: 128 threads, one (b, d) lane per thread.
__global__ void __launch_bounds__(128) scan_kernel(const float* __restrict__ u,
                                                   const float* __restrict__ delta,
                                                   const float* __restrict__ xdbl,
                                                   const float* __restrict__ xz,
                                                   const float* __restrict__ A_log,
                                                   const float* __restrict__ Dskip,
                                                   float* __restrict__ y)
{
    int d = blockIdx.x * 128 + threadIdx.x;
    int b = blockIdx.y;

    float Aa[DS];
    #pragma unroll
    for (int n = 0; n < DS; n++)
        Aa[n] = -__expf(A_log[(size_t)d * DS + n]);
    float Dd = Dskip[d];

    float h[DS];
    #pragma unroll
    for (int n = 0; n < DS; n++) h[n] = 0.0f;

    __shared__ float sBC[64][32];   // per step: [0:16)=B, [16:32)=C
    const float* xdbl_b = xdbl + (size_t)b * LL * XD;

    for (int l0 = 0; l0 < LL; l0 += 64) {
        __syncthreads();
        for (int i = threadIdx.x; i < 64 * 32; i += 128) {
            int row = i >> 5;
            int c   = i & 31;
            sBC[row][c] = xdbl_b[(size_t)(l0 + row) * XD + DTR + c];
        }
        __syncthreads();
        for (int i = 0; i < 64; i++) {
            size_t t = (size_t)b * LL + l0 + i;
            float dlt = delta[t * DI + d];
            float uu  = u[t * DI + d];
            float du  = dlt * uu;
            float yv  = 0.0f;
            #pragma unroll
            for (int n = 0; n < DS; n++) {
                h[n] = h[n] * __expf(dlt * Aa[n]) + du * sBC[i][n];
                yv   = fmaf(h[n], sBC[i][DS + n], yv);
            }
            float z = xz[t * (2 * DI) + DI + d];
            y[t * DI + d] = (yv + uu * Dd) * silu_f(z);
        }
    }
}

// ---------------- host launcher ----------------
extern "C" void kernel_launch(void* const* d_in, const int* in_sizes, int n_in,
                              void* d_out, int out_size)
{
    (void)in_sizes; (void)n_in; (void)out_size;

    const int*   ids       = (const int*)  d_in[0];
    const float* times     = (const float*)d_in[1];
    /* d_in[2] attention_mask unused */
    const float* embed     = (const float*)d_in[3];
    const float* time_w    = (const float*)d_in[4];
    const float* time_b    = (const float*)d_in[5];
    const float* in_proj_w = (const float*)d_in[6];
    const float* conv_w    = (const float*)d_in[7];
    const float* conv_b    = (const float*)d_in[8];
    const float* x_proj_w  = (const float*)d_in[9];
    const float* dt_proj_w = (const float*)d_in[10];
    const float* dt_proj_b = (const float*)d_in[11];
    const float* A_log     = (const float*)d_in[12];
    const float* Dskip     = (const float*)d_in[13];
    const float* out_proj_w= (const float*)d_in[14];
    const float* norm_w    = (const float*)d_in[15];
    const float* norm_f_w  = (const float*)d_in[16];
    float* out = (float*)d_out;

    float *h, *xn, *xz, *x, *xdbl, *delta, *y;
    cudaGetSymbolAddress((void**)&h,     g_h);
    cudaGetSymbolAddress((void**)&xn,    g_xn);
    cudaGetSymbolAddress((void**)&xz,    g_xz);
    cudaGetSymbolAddress((void**)&x,     g_x);
    cudaGetSymbolAddress((void**)&xdbl,  g_xdbl);
    cudaGetSymbolAddress((void**)&delta, g_delta);
    cudaGetSymbolAddress((void**)&y,     g_y);

    // embedding + time embedding
    {
        int n = MTOT * DM;
        embed_kernel<<<(n + 255) / 256, 256>>>(ids, times, embed, time_w, time_b, h);
    }

    for (int layer = 0; layer < NL; layer++) {
        const float* inw = in_proj_w  + (size_t)layer * 2 * DI * DM;
        const float* cw  = conv_w     + (size_t)layer * DI * DCONV;
        const float* cb  = conv_b     + (size_t)layer * DI;
        const float* xw  = x_proj_w   + (size_t)layer * XD * DI;
        const float* dtw = dt_proj_w  + (size_t)layer * DI * DTR;
        const float* dtb = dt_proj_b  + (size_t)layer * DI;
        const float* Al  = A_log      + (size_t)layer * DI * DS;
        const float* Dl  = Dskip      + (size_t)layer * DI;
        const float* ow  = out_proj_w + (size_t)layer * DM * DI;
        const float* nw  = norm_w     + (size_t)layer * DM;

        // rmsnorm
        rmsnorm_kernel<<<MTOT, 256>>>(h, nw, xn);

        // in_proj: [16384,768] @ [3072,768]^T -> xz [16384,3072]
        {
            dim3 grid((2 * DI + 127) / 128, MTOT / 128);
            gemm_nt<false, false, false><<<grid, 256>>>(
                xn, inw, xz, MTOT, 2 * DI, DM, DM, 2 * DI, nullptr);
        }

        // conv + silu -> x (u)
        {
            int n = MTOT * DI;
            conv_silu_kernel<<<(n + 255) / 256, 256>>>(xz, cw, cb, x);
        }

        // x_proj: [16384,1536] @ [80,1536]^T -> xdbl [16384,80]
        {
            dim3 grid((XD + 127) / 128, MTOT / 128);
            gemm_nt<false, false, false><<<grid, 256>>>(
                x, xw, xdbl, MTOT, XD, DI, DI, XD, nullptr);
        }

        // dt_proj + bias + softplus: [16384,48] @ [1536,48]^T -> delta
        {
            dim3 grid((DI + 127) / 128, MTOT / 128);
            gemm_nt<true, true, false><<<grid, 256>>>(
                xdbl, dtw, delta, MTOT, DI, DTR, XD, DI, dtb);
        }

        // selective scan (fused D skip + silu(z) gate) -> y
        {
            dim3 grid(DI / 128, BB);
            scan_kernel<<<grid, 128>>>(x, delta, xdbl, xz, Al, Dl, y);
        }

        // out_proj with residual: h += y @ ow^T   [16384,1536] @ [768,1536]^T
        {
            dim3 grid((DM + 127) / 128, MTOT / 128);
            gemm_nt<false, false, true><<<grid, 256>>>(
                y, ow, h, MTOT, DM, DI, DI, DM, nullptr);
        }
    }

    // final rmsnorm
    rmsnorm_kernel<<<MTOT, 256>>>(h, norm_f_w, xn);

    // logits: [16384,768] @ [1969,768]^T -> out [16384,1969]
    {
        dim3 grid((VOCABN + 127) / 128, MTOT / 128);
        gemm_nt<false, false, false><<<grid, 256>>>(
            xn, embed, out, MTOT, VOCABN, DM, DM, VOCABN, nullptr);
    }
}

// round 10
// speedup vs baseline: 1.5047x; 1.5047x over previous
#include <cuda_runtime.h>
#include <cuda_bf16.h>
#include <math.h>
#include <stdint.h>

// ---------------- problem constants ----------------
#define BB    8
#define LL    2048
#define VOCABN 1969
#define DM    768
#define NL    4
#define DI    1536
#define DS    16
#define DCONV 4
#define DTR   48
#define MTOT  (BB*LL)          // 16384
#define XD    80               // DT_RANK + 2*D_STATE
#define EPSV  1e-5f

// ---------------- scratch (device globals; no allocs allowed) ----------------
__device__ float g_h    [MTOT*DM];       // residual stream
__device__ float g_xn   [MTOT*DM];       // rmsnorm output
__device__ float g_xz   [MTOT*2*DI];     // in_proj output
__device__ float g_x    [MTOT*DI];       // conv+silu output (u)
__device__ float g_xdbl [MTOT*XD];       // x_proj output (dt | B | C)
__device__ float g_delta[MTOT*DI];       // softplus(dt_proj)
__device__ float g_y    [MTOT*DI];       // scan output (gated)

// ---------------- helpers ----------------
__device__ __forceinline__ float silu_f(float v) {
    return v / (1.0f + __expf(-v));
}
__device__ __forceinline__ float softplus_f(float v) {
    return fmaxf(v, 0.0f) + log1pf(__expf(-fabsf(v)));
}
__device__ __forceinline__ uint32_t f2tf32(float f) {
    uint32_t r;
    asm("cvt.rna.tf32.f32 %0, %1;" : "=r"(r) : "f"(f));
    return r;
}
__device__ __forceinline__ void mma_tf32(float* c, const uint32_t* a, const uint32_t* b) {
    asm volatile(
        "mma.sync.aligned.m16n8k8.row.col.f32.tf32.tf32.f32 "
        "{%0,%1,%2,%3}, {%4,%5,%6,%7}, {%8,%9}, {%0,%1,%2,%3};\n"
        : "+f"(c[0]), "+f"(c[1]), "+f"(c[2]), "+f"(c[3])
        : "r"(a[0]), "r"(a[1]), "r"(a[2]), "r"(a[3]),
          "r"(b[0]), "r"(b[1]));
}

// ---------------- embedding + time embedding ----------------
__global__ void embed_kernel(const int* __restrict__ ids,
                             const float* __restrict__ times,
                             const float* __restrict__ embed,
                             const float* __restrict__ time_w,
                             const float* __restrict__ time_b,
                             float* __restrict__ h)
{
    int idx = blockIdx.x * blockDim.x + threadIdx.x;
    if (idx >= MTOT * DM) return;
    int t = idx / DM;
    int d = idx - t * DM;
    int tok = ids[t];
    h[idx] = embed[(size_t)tok * DM + d] + times[t] * time_w[d] + time_b[d];
}

// ---------------- rmsnorm (one block per row of 768) ----------------
__global__ void __launch_bounds__(256) rmsnorm_kernel(const float* __restrict__ in,
                                                      const float* __restrict__ w,
                                                      float* __restrict__ out)
{
    __shared__ float red[256];
    int r = blockIdx.x;
    int tid = threadIdx.x;
    const float* row = in + (size_t)r * DM;
    float v0 = row[tid];
    float v1 = row[tid + 256];
    float v2 = row[tid + 512];
    float ss = v0*v0 + v1*v1 + v2*v2;
    red[tid] = ss;
    __syncthreads();
    for (int s = 128; s > 0; s >>= 1) {
        if (tid < s) red[tid] += red[tid + s];
        __syncthreads();
    }
    float scale = rsqrtf(red[0] * (1.0f / DM) + EPSV);
    float* orow = out + (size_t)r * DM;
    orow[tid]       = v0 * scale * w[tid];
    orow[tid + 256] = v1 * scale * w[tid + 256];
    orow[tid + 512] = v2 * scale * w[tid + 512];
}

// =====================================================================
// TF32 tensor-core NT GEMM: C[M,N] = A[M,K] @ W[N,K]^T
// Block tile 128x128, BK=16, 256 threads (8 warps of 64x32 warp tiles).
// mma.sync.m16n8k8 tf32. Inputs rounded to tf32 (rna) at smem store.
// Requirements (all call sites satisfy): M%128==0, K%16==0, lda%4==0.
// N guarded. Transposed smem [k][m] with pad 4.
// =====================================================================
#define GBM 128
#define GBN 128
#define GBK 16
#define GPAD 132      // 128 + 4

template<bool BIAS, bool SOFTPLUS, bool RESID>
__global__ void __launch_bounds__(256) gemm_tf32(const float* __restrict__ A,
                                                 const float* __restrict__ W,
                                                 float* __restrict__ C,
                                                 int M, int N, int K,
                                                 int lda, int ldc,
                                                 const float* __restrict__ bias)
{
    __shared__ uint32_t As[2][GBK][GPAD];
    __shared__ uint32_t Bs[2][GBK][GPAD];

    const int tid  = threadIdx.x;
    const int warp = tid >> 5;
    const int lane = tid & 31;
    const int g    = lane >> 2;     // 0..7
    const int t    = lane & 3;      // 0..3
    const int wy   = warp >> 2;     // 0..1 -> m offset 64
    const int wx   = warp & 3;      // 0..3 -> n offset 32
    const int wm0  = wy * 64;
    const int wn0  = wx * 32;

    const int bm = blockIdx.y * GBM;
    const int bn = blockIdx.x * GBN;

    // gmem load mapping: 2 threads per row, 8 floats each (2 float4)
    const int lrow = tid >> 1;            // 0..127
    const int lcol = (tid & 1) * 8;       // 0 or 8

    const float* Aptr = A + (size_t)(bm + lrow) * lda + lcol;
    const float* Bptr = W + (size_t)(bn + lrow) * K   + lcol;
    const bool bvalid = (bn + lrow) < N;

    float acc[4][4][4];
    #pragma unroll
    for (int i = 0; i < 4; i++)
        #pragma unroll
        for (int j = 0; j < 4; j++)
            #pragma unroll
            for (int r = 0; r < 4; r++)
                acc[i][j][r] = 0.0f;

    // ---- prologue: load tile 0 ----
    float4 av0 = *(const float4*)(Aptr);
    float4 av1 = *(const float4*)(Aptr + 4);
    float4 bv0 = bvalid ? *(const float4*)(Bptr)     : make_float4(0.f,0.f,0.f,0.f);
    float4 bv1 = bvalid ? *(const float4*)(Bptr + 4) : make_float4(0.f,0.f,0.f,0.f);

    As[0][lcol + 0][lrow] = f2tf32(av0.x);
    As[0][lcol + 1][lrow] = f2tf32(av0.y);
    As[0][lcol + 2][lrow] = f2tf32(av0.z);
    As[0][lcol + 3][lrow] = f2tf32(av0.w);
    As[0][lcol + 4][lrow] = f2tf32(av1.x);
    As[0][lcol + 5][lrow] = f2tf32(av1.y);
    As[0][lcol + 6][lrow] = f2tf32(av1.z);
    As[0][lcol + 7][lrow] = f2tf32(av1.w);
    Bs[0][lcol + 0][lrow] = f2tf32(bv0.x);
    Bs[0][lcol + 1][lrow] = f2tf32(bv0.y);
    Bs[0][lcol + 2][lrow] = f2tf32(bv0.z);
    Bs[0][lcol + 3][lrow] = f2tf32(bv0.w);
    Bs[0][lcol + 4][lrow] = f2tf32(bv1.x);
    Bs[0][lcol + 5][lrow] = f2tf32(bv1.y);
    Bs[0][lcol + 6][lrow] = f2tf32(bv1.z);
    Bs[0][lcol + 7][lrow] = f2tf32(bv1.w);
    __syncthreads();

    int buf = 0;
    for (int k0 = 0; k0 < K; k0 += GBK) {
        const bool has_next = (k0 + GBK) < K;
        if (has_next) {
            const float* Ap = Aptr + k0 + GBK;
            const float* Bp = Bptr + k0 + GBK;
            av0 = *(const float4*)(Ap);
            av1 = *(const float4*)(Ap + 4);
            bv0 = bvalid ? *(const float4*)(Bp)     : make_float4(0.f,0.f,0.f,0.f);
            bv1 = bvalid ? *(const float4*)(Bp + 4) : make_float4(0.f,0.f,0.f,0.f);
        }

        // ---- compute on smem[buf] ----
        #pragma unroll
        for (int ks = 0; ks < 2; ks++) {
            const int kk = ks * 8;
            uint32_t af[4][4], bf[4][2];
            #pragma unroll
            for (int mt = 0; mt < 4; mt++) {
                const int m = wm0 + mt * 16 + g;
                af[mt][0] = As[buf][kk + t    ][m];
                af[mt][1] = As[buf][kk + t    ][m + 8];
                af[mt][2] = As[buf][kk + t + 4][m];
                af[mt][3] = As[buf][kk + t + 4][m + 8];
            }
            #pragma unroll
            for (int nt = 0; nt < 4; nt++) {
                const int n = wn0 + nt * 8 + g;
                bf[nt][0] = Bs[buf][kk + t    ][n];
                bf[nt][1] = Bs[buf][kk + t + 4][n];
            }
            #pragma unroll
            for (int mt = 0; mt < 4; mt++)
                #pragma unroll
                for (int nt = 0; nt < 4; nt++)
                    mma_tf32(acc[mt][nt], af[mt], bf[nt]);
        }

        if (has_next) {
            const int nb = buf ^ 1;
            As[nb][lcol + 0][lrow] = f2tf32(av0.x);
            As[nb][lcol + 1][lrow] = f2tf32(av0.y);
            As[nb][lcol + 2][lrow] = f2tf32(av0.z);
            As[nb][lcol + 3][lrow] = f2tf32(av0.w);
            As[nb][lcol + 4][lrow] = f2tf32(av1.x);
            As[nb][lcol + 5][lrow] = f2tf32(av1.y);
            As[nb][lcol + 6][lrow] = f2tf32(av1.z);
            As[nb][lcol + 7][lrow] = f2tf32(av1.w);
            Bs[nb][lcol + 0][lrow] = f2tf32(bv0.x);
            Bs[nb][lcol + 1][lrow] = f2tf32(bv0.y);
            Bs[nb][lcol + 2][lrow] = f2tf32(bv0.z);
            Bs[nb][lcol + 3][lrow] = f2tf32(bv0.w);
            Bs[nb][lcol + 4][lrow] = f2tf32(bv1.x);
            Bs[nb][lcol + 5][lrow] = f2tf32(bv1.y);
            Bs[nb][lcol + 6][lrow] = f2tf32(bv1.z);
            Bs[nb][lcol + 7][lrow] = f2tf32(bv1.w);
            __syncthreads();
            buf = nb;
        }
    }

    // ---- epilogue ----
    #pragma unroll
    for (int mt = 0; mt < 4; mt++) {
        const int mrow0 = bm + wm0 + mt * 16 + g;
        #pragma unroll
        for (int nt = 0; nt < 4; nt++) {
            const int ncol0 = bn + wn0 + nt * 8 + 2 * t;
            #pragma unroll
            for (int half = 0; half < 2; half++) {
                const int m = mrow0 + half * 8;
                #pragma unroll
                for (int e = 0; e < 2; e++) {
                    const int n = ncol0 + e;
                    if (n < N) {
                        float v = acc[mt][nt][half * 2 + e];
                        if (BIAS)     v += bias[n];
                        if (SOFTPLUS) v = softplus_f(v);
                        const size_t idx = (size_t)m * ldc + n;
                        if (RESID)    v += C[idx];
                        C[idx] = v;
                    }
                }
            }
        }
    }
}

// ---------------- causal depthwise conv (width 4) + silu ----------------
__global__ void conv_silu_kernel(const float* __restrict__ xz,
                                 const float* __restrict__ cw,
                                 const float* __restrict__ cb,
                                 float* __restrict__ x)
{
    int idx = blockIdx.x * blockDim.x + threadIdx.x;
    if (idx >= MTOT * DI) return;
    int t = idx / DI;
    int d = idx - t * DI;
    int l = t & (LL - 1);          // L = 2048 power of two
    float w0 = cw[d * DCONV + 0];
    float w1 = cw[d * DCONV + 1];
    float w2 = cw[d * DCONV + 2];
    float w3 = cw[d * DCONV + 3];
    float acc = cb[d];
    const float* base = xz + (size_t)t * (2 * DI) + d;
    if (l >= 3) acc += base[-3 * 2 * DI] * w0;
    if (l >= 2) acc += base[-2 * 2 * DI] * w1;
    if (l >= 1) acc += base[-1 * 2 * DI] * w2;
    acc += base[0] * w3;
    x[idx] = silu_f(acc);
}

// ---------------- selective scan (fused D-skip + z gate) ----------------
// grid: (DI/32, B), block: 32 threads (one warp), one (b, d) lane per thread.
__global__ void __launch_bounds__(32) scan_kernel(const float* __restrict__ u,
                                                  const float* __restrict__ delta,
                                                  const float* __restrict__ xdbl,
                                                  const float* __restrict__ xz,
                                                  const float* __restrict__ A_log,
                                                  const float* __restrict__ Dskip,
                                                  float* __restrict__ y)
{
    int d = blockIdx.x * 32 + threadIdx.x;
    int b = blockIdx.y;

    float Aa[DS];
    #pragma unroll
    for (int n = 0; n < DS; n++)
        Aa[n] = -__expf(A_log[(size_t)d * DS + n]);
    float Dd = Dskip[d];

    float h[DS];
    #pragma unroll
    for (int n = 0; n < DS; n++) h[n] = 0.0f;

    __shared__ float sBC[64][32];   // per step: [0:16)=B, [16:32)=C
    const float* xdbl_b = xdbl + (size_t)b * LL * XD;

    for (int l0 = 0; l0 < LL; l0 += 64) {
        __syncwarp();
        for (int i = threadIdx.x; i < 64 * 32; i += 32) {
            int row = i >> 5;
            int c   = i & 31;
            sBC[row][c] = xdbl_b[(size_t)(l0 + row) * XD + DTR + c];
        }
        __syncwarp();
        for (int i = 0; i < 64; i++) {
            size_t t = (size_t)b * LL + l0 + i;
            float dlt = delta[t * DI + d];
            float uu  = u[t * DI + d];
            float du  = dlt * uu;
            float yv  = 0.0f;
            #pragma unroll
            for (int n = 0; n < DS; n++) {
                h[n] = h[n] * __expf(dlt * Aa[n]) + du * sBC[i][n];
                yv   = fmaf(h[n], sBC[i][DS + n], yv);
            }
            float z = xz[t * (2 * DI) + DI + d];
            y[t * DI + d] = (yv + uu * Dd) * silu_f(z);
        }
    }
}

// ---------------- host launcher ----------------
extern "C" void kernel_launch(void* const* d_in, const int* in_sizes, int n_in,
                              void* d_out, int out_size)
{
    (void)in_sizes; (void)n_in; (void)out_size;

    const int*   ids       = (const int*)  d_in[0];
    const float* times     = (const float*)d_in[1];
    /* d_in[2] attention_mask unused */
    const float* embed     = (const float*)d_in[3];
    const float* time_w    = (const float*)d_in[4];
    const float* time_b    = (const float*)d_in[5];
    const float* in_proj_w = (const float*)d_in[6];
    const float* conv_w    = (const float*)d_in[7];
    const float* conv_b    = (const float*)d_in[8];
    const float* x_proj_w  = (const float*)d_in[9];
    const float* dt_proj_w = (const float*)d_in[10];
    const float* dt_proj_b = (const float*)d_in[11];
    const float* A_log     = (const float*)d_in[12];
    const float* Dskip     = (const float*)d_in[13];
    const float* out_proj_w= (const float*)d_in[14];
    const float* norm_w    = (const float*)d_in[15];
    const float* norm_f_w  = (const float*)d_in[16];
    float* out = (float*)d_out;

    float *h, *xn, *xz, *x, *xdbl, *delta, *y;
    cudaGetSymbolAddress((void**)&h,     g_h);
    cudaGetSymbolAddress((void**)&xn,    g_xn);
    cudaGetSymbolAddress((void**)&xz,    g_xz);
    cudaGetSymbolAddress((void**)&x,     g_x);
    cudaGetSymbolAddress((void**)&xdbl,  g_xdbl);
    cudaGetSymbolAddress((void**)&delta, g_delta);
    cudaGetSymbolAddress((void**)&y,     g_y);

    // embedding + time embedding
    {
        int n = MTOT * DM;
        embed_kernel<<<(n + 255) / 256, 256>>>(ids, times, embed, time_w, time_b, h);
    }

    for (int layer = 0; layer < NL; layer++) {
        const float* inw = in_proj_w  + (size_t)layer * 2 * DI * DM;
        const float* cw  = conv_w     + (size_t)layer * DI * DCONV;
        const float* cb  = conv_b     + (size_t)layer * DI;
        const float* xw  = x_proj_w   + (size_t)layer * XD * DI;
        const float* dtw = dt_proj_w  + (size_t)layer * DI * DTR;
        const float* dtb = dt_proj_b  + (size_t)layer * DI;
        const float* Al  = A_log      + (size_t)layer * DI * DS;
        const float* Dl  = Dskip      + (size_t)layer * DI;
        const float* ow  = out_proj_w + (size_t)layer * DM * DI;
        const float* nw  = norm_w     + (size_t)layer * DM;

        // rmsnorm
        rmsnorm_kernel<<<MTOT, 256>>>(h, nw, xn);

        // in_proj: [16384,768] @ [3072,768]^T -> xz [16384,3072]
        {
            dim3 grid((2 * DI + GBN - 1) / GBN, MTOT / GBM);
            gemm_tf32<false, false, false><<<grid, 256>>>(
                xn, inw, xz, MTOT, 2 * DI, DM, DM, 2 * DI, nullptr);
        }

        // conv + silu -> x (u)
        {
            int n = MTOT * DI;
            conv_silu_kernel<<<(n + 255) / 256, 256>>>(xz, cw, cb, x);
        }

        // x_proj: [16384,1536] @ [80,1536]^T -> xdbl [16384,80]
        {
            dim3 grid((XD + GBN - 1) / GBN, MTOT / GBM);
            gemm_tf32<false, false, false><<<grid, 256>>>(
                x, xw, xdbl, MTOT, XD, DI, DI, XD, nullptr);
        }

        // dt_proj + bias + softplus: [16384,48] @ [1536,48]^T -> delta
        {
            dim3 grid((DI + GBN - 1) / GBN, MTOT / GBM);
            gemm_tf32<true, true, false><<<grid, 256>>>(
                xdbl, dtw, delta, MTOT, DI, DTR, XD, DI, dtb);
        }

        // selective scan (fused D skip + silu(z) gate) -> y
        {
            dim3 grid(DI / 32, BB);
            scan_kernel<<<grid, 32>>>(x, delta, xdbl, xz, Al, Dl, y);
        }

        // out_proj with residual: h += y @ ow^T   [16384,1536] @ [768,1536]^T
        {
            dim3 grid((DM + GBN - 1) / GBN, MTOT / GBM);
            gemm_tf32<false, false, true><<<grid, 256>>>(
                y, ow, h, MTOT, DM, DI, DI, DM, nullptr);
        }
    }

    // final rmsnorm
    rmsnorm_kernel<<<MTOT, 256>>>(h, norm_f_w, xn);

    // logits: [16384,768] @ [1969,768]^T -> out [16384,1969]
    {
        dim3 grid((VOCABN + GBN - 1) / GBN, MTOT / GBM);
        gemm_tf32<false, false, false><<<grid, 256>>>(
            xn, embed, out, MTOT, VOCABN, DM, DM, VOCABN, nullptr);
    }
}